// round 7
// baseline (speedup 1.0000x reference)
#include <cuda_runtime.h>
#include <cuda_fp16.h>
#include <math.h>
#include <stdint.h>

#define NN    100000
#define EE    3200000
#define FIN   512
#define HIDD  256
#define NCLS  64
#define NITER 10

// ---------------- device scratch (static, no runtime allocation) -------------
__device__ int   g_deg[NN];          // in-degree incl. self loop
__device__ int   g_rowptr[NN + 1];   // CSR row pointers (real edges only)
__device__ int   g_fill[NN];         // scatter cursors
__device__ int2  g_srcw[EE];         // per-edge (source id, dinv[source] bits)
__device__ float g_dinv[NN];         // rsqrt(deg)
__device__ float g_q[NN];            // running halting remainder
__device__ float g_h1[(size_t)NN * HIDD]; // MLP hidden activations
__device__ uint2 g_hf[2][(size_t)NN * 16]; // fp16 ping-pong mirror of iterate

// ---------------- preprocessing ---------------------------------------------
__global__ void k_init() {
    int i = blockIdx.x * blockDim.x + threadIdx.x;
    if (i < NN) { g_deg[i] = 1; g_fill[i] = 0; g_q[i] = 1.0f; }
}

__global__ void k_hist(const int* __restrict__ ei) {
    int e = blockIdx.x * blockDim.x + threadIdx.x;
    if (e < EE) atomicAdd(&g_deg[ei[EE + e]], 1);   // col = target
}

// single-block scan over (deg-1); also computes dinv
__global__ void k_scan() {
    __shared__ int partial[1024];
    const int CH = (NN + 1023) / 1024;      // 98
    int t = threadIdx.x;
    int beg = t * CH;
    int end = min(NN, beg + CH);
    int sum = 0;
    for (int i = beg; i < end; i++) sum += g_deg[i] - 1;
    partial[t] = sum;
    __syncthreads();
    for (int off = 1; off < 1024; off <<= 1) {
        int v = (t >= off) ? partial[t - off] : 0;
        __syncthreads();
        partial[t] += v;
        __syncthreads();
    }
    int excl = (t == 0) ? 0 : partial[t - 1];
    for (int i = beg; i < end; i++) {
        g_rowptr[i] = excl;
        excl += g_deg[i] - 1;
        g_dinv[i] = rsqrtf((float)g_deg[i]);
    }
    if (end == NN) g_rowptr[NN] = excl;     // all tail threads write same total
}

__global__ void k_scatter(const int* __restrict__ ei) {
    int e = blockIdx.x * blockDim.x + threadIdx.x;
    if (e < EE) {
        int c = ei[EE + e];
        int s = ei[e];
        int p = g_rowptr[c] + atomicAdd(&g_fill[c], 1);
        g_srcw[p] = make_int2(s, __float_as_int(g_dinv[s]));
    }
}

// ---------------- tf32 helpers -----------------------------------------------
__device__ __forceinline__ uint32_t f2tf32(float x) {
    uint32_t u;
    asm("cvt.rna.tf32.f32 %0, %1;" : "=r"(u) : "f"(x));
    return u;
}

__device__ __forceinline__ void mma_tf32(float c[4],
                                         uint32_t a0, uint32_t a1, uint32_t a2, uint32_t a3,
                                         uint32_t b0, uint32_t b1) {
    asm volatile("mma.sync.aligned.m16n8k8.row.col.f32.tf32.tf32.f32 "
                 "{%0,%1,%2,%3}, {%4,%5,%6,%7}, {%8,%9}, {%0,%1,%2,%3};"
                 : "+f"(c[0]), "+f"(c[1]), "+f"(c[2]), "+f"(c[3])
                 : "r"(a0), "r"(a1), "r"(a2), "r"(a3), "r"(b0), "r"(b1));
}

__device__ __forceinline__ uint2 pack_half4(float4 o) {
    __half2 p0 = __floats2half2_rn(o.x, o.y);
    __half2 p1 = __floats2half2_rn(o.z, o.w);
    uint2 hv;
    hv.x = *(unsigned*)&p0;
    hv.y = *(unsigned*)&p1;
    return hv;
}

// ---------------- MLP1: h1 = relu(x @ W1 + b1), tf32 tensor cores ------------
// 128x128 block tile, BK=16 double-buffered, 8 warps of 64x32.
// grid = (HIDD/128, NN/128): consecutive CTAs share the same X row-tile -> L2 reuse.
#define APAD 20     // As row stride (floats): banks (20g+t)%32 unique -> conflict-free
#define BPAD 136    // Bs row stride (floats): banks (8t+g)%32 unique -> conflict-free
__global__ void __launch_bounds__(256) k_mm1(const float* __restrict__ X,
                                             const float* __restrict__ W1,
                                             const float* __restrict__ b1) {
    __shared__ uint32_t As[2][128][APAD];   // [m][k], tf32 bits
    __shared__ uint32_t Bs[2][16][BPAD];    // [k][n], tf32 bits
    const int bn = blockIdx.x * 128;
    const int bm = blockIdx.y * 128;
    const int tid = threadIdx.x;
    const int wid = tid >> 5, lane = tid & 31;
    const int g = lane >> 2, t = lane & 3;          // groupID, thread-in-group
    const int wm0 = (wid & 1) * 64;                 // warp M origin within block
    const int wn0 = (wid >> 1) * 32;                // warp N origin within block

    float acc[4][4][4] = {};                        // [mt][nt][c0..3]

    // stage loader: gmem -> smem(buf) for k-slice k0
    auto load_stage = [&](int buf, int k0) {
        #pragma unroll
        for (int r = 0; r < 2; r++) {
            int f = tid + r * 256;                  // A: 512 float4
            int row = f >> 2;                       // 4 float4 per 16-wide row
            int kk = (f & 3) * 4;
            int gm = min(bm + row, NN - 1);
            float4 v = *(const float4*)(X + (size_t)gm * FIN + k0 + kk);
            As[buf][row][kk + 0] = f2tf32(v.x);
            As[buf][row][kk + 1] = f2tf32(v.y);
            As[buf][row][kk + 2] = f2tf32(v.z);
            As[buf][row][kk + 3] = f2tf32(v.w);
        }
        #pragma unroll
        for (int r = 0; r < 2; r++) {
            int f = tid + r * 256;                  // B: 512 float4
            int row = f >> 5;                       // 32 float4 per 128-wide row
            int nn = (f & 31) * 4;
            float4 v = *(const float4*)(W1 + (size_t)(k0 + row) * HIDD + bn + nn);
            Bs[buf][row][nn + 0] = f2tf32(v.x);
            Bs[buf][row][nn + 1] = f2tf32(v.y);
            Bs[buf][row][nn + 2] = f2tf32(v.z);
            Bs[buf][row][nn + 3] = f2tf32(v.w);
        }
    };

    load_stage(0, 0);
    __syncthreads();

    const int NSTAGE = FIN / 16;                    // 32
    for (int st = 0; st < NSTAGE; st++) {
        int buf = st & 1;
        if (st + 1 < NSTAGE) load_stage(buf ^ 1, (st + 1) * 16);

        #pragma unroll
        for (int ks = 0; ks < 2; ks++) {
            int kc = ks * 8;
            uint32_t af[4][4];                      // [mt][0..3]
            #pragma unroll
            for (int mt = 0; mt < 4; mt++) {
                int r = wm0 + mt * 16 + g;
                af[mt][0] = As[buf][r][kc + t];
                af[mt][1] = As[buf][r + 8][kc + t];
                af[mt][2] = As[buf][r][kc + t + 4];
                af[mt][3] = As[buf][r + 8][kc + t + 4];
            }
            #pragma unroll
            for (int nt = 0; nt < 4; nt++) {
                int n = wn0 + nt * 8 + g;
                uint32_t b0 = Bs[buf][kc + t][n];
                uint32_t b1f = Bs[buf][kc + t + 4][n];
                #pragma unroll
                for (int mt = 0; mt < 4; mt++)
                    mma_tf32(acc[mt][nt], af[mt][0], af[mt][1], af[mt][2], af[mt][3], b0, b1f);
            }
        }
        __syncthreads();
    }

    // epilogue: bias + relu, direct float2 stores
    #pragma unroll
    for (int nt = 0; nt < 4; nt++) {
        int n = bn + wn0 + nt * 8 + 2 * t;
        float bx = b1[n], by = b1[n + 1];
        #pragma unroll
        for (int mt = 0; mt < 4; mt++) {
            int m0 = bm + wm0 + mt * 16 + g;
            if (m0 < NN) {
                float2 o;
                o.x = fmaxf(acc[mt][nt][0] + bx, 0.0f);
                o.y = fmaxf(acc[mt][nt][1] + by, 0.0f);
                *(float2*)(g_h1 + (size_t)m0 * HIDD + n) = o;
            }
            int m1 = m0 + 8;
            if (m1 < NN) {
                float2 o;
                o.x = fmaxf(acc[mt][nt][2] + bx, 0.0f);
                o.y = fmaxf(acc[mt][nt][3] + by, 0.0f);
                *(float2*)(g_h1 + (size_t)m1 * HIDD + n) = o;
            }
        }
    }
}

// ---------------- MLP2: pred0 = h1 @ W2 + b2 (+ fp16 mirror seed) -----------
// 64-node tile x full 64 cols, BK=64, 256 threads, 4x4 microtile
__global__ void __launch_bounds__(256) k_mm2(const float* __restrict__ W2,
                                             const float* __restrict__ b2,
                                             float* __restrict__ out) {
    __shared__ float Hs[64][64];    // [k][m]
    __shared__ float Ws[64][64];    // [k][n]
    int bm = blockIdx.x * 64;
    int tid = threadIdx.x;
    int tx = tid & 15, ty = tid >> 4;
    float acc[4][4] = {};
    for (int kc = 0; kc < HIDD; kc += 64) {
        #pragma unroll
        for (int r = 0; r < 4; r++) {
            int f = tid + r * 256;          // float4 index 0..1023
            int row = f >> 4;
            int kk = (f & 15) * 4;
            int gm = min(bm + row, NN - 1);
            float4 v = *(const float4*)(g_h1 + (size_t)gm * HIDD + kc + kk);
            Hs[kk + 0][row] = v.x; Hs[kk + 1][row] = v.y;
            Hs[kk + 2][row] = v.z; Hs[kk + 3][row] = v.w;
            float4 wv = *(const float4*)(W2 + (size_t)(kc + row) * NCLS + kk);
            *(float4*)&Ws[row][kk] = wv;
        }
        __syncthreads();
        #pragma unroll
        for (int k = 0; k < 64; k++) {
            float4 av = *(const float4*)&Hs[k][ty * 4];
            float4 bv = *(const float4*)&Ws[k][tx * 4];
            float ra[4] = {av.x, av.y, av.z, av.w};
            float rb[4] = {bv.x, bv.y, bv.z, bv.w};
            #pragma unroll
            for (int i = 0; i < 4; i++)
                #pragma unroll
                for (int j = 0; j < 4; j++)
                    acc[i][j] += ra[i] * rb[j];
        }
        __syncthreads();
    }
    #pragma unroll
    for (int i = 0; i < 4; i++) {
        int m = bm + ty * 4 + i;
        if (m >= NN) continue;
        int n = tx * 4;
        float4 o;
        o.x = acc[i][0] + b2[n + 0];
        o.y = acc[i][1] + b2[n + 1];
        o.z = acc[i][2] + b2[n + 2];
        o.w = acc[i][3] + b2[n + 3];
        *(float4*)(out + (size_t)m * NCLS + n) = o;
        g_hf[0][(size_t)m * 16 + (n >> 2)] = pack_half4(o);   // seed fp16 mirror
    }
}

// ---------------- propagation: fp16 gathers, fp32 math/outputs ---------------
// One warp per node, 2 edges/step; lanes split in halves of 16; each half-lane
// loads 4 cols as fp16 (8B). Metadata via broadcast LDG. fp32 slice written as
// output; fp16 mirror written for next iteration's gather.
__global__ void __launch_bounds__(256) k_prop(const float* __restrict__ ch,
                                              float* __restrict__ nh,
                                              float* __restrict__ p_out,
                                              const float* __restrict__ hw,
                                              const float* __restrict__ hb,
                                              int it) {
    int warp = (blockIdx.x * blockDim.x + threadIdx.x) >> 5;
    if (warp >= NN) return;
    const int lane = threadIdx.x & 31;
    const int half = lane >> 4;          // 0 or 1
    const int cl   = lane & 15;          // 4-col group index 0..15
    const int node = warp;
    const int beg = g_rowptr[node];
    const int end = g_rowptr[node + 1];
    const uint2* __restrict__ cur = g_hf[it & 1];
    uint2* __restrict__ nxt = g_hf[(it + 1) & 1];

    float4 acc = make_float4(0.0f, 0.0f, 0.0f, 0.0f);
    #pragma unroll 4
    for (int j0 = beg; j0 < end; j0 += 2) {
        int j = j0 + half;
        int s = node; float w = 0.0f;    // safe defaults for tail
        if (j < end) {
            int2 sw = g_srcw[j];         // broadcast within each half
            s = sw.x; w = __int_as_float(sw.y);
        }
        uint2 hv = cur[(size_t)s * 16 + cl];
        __half2 h0 = *(__half2*)&hv.x;
        __half2 h1 = *(__half2*)&hv.y;
        float2 f0 = __half22float2(h0);
        float2 f1 = __half22float2(h1);
        acc.x += w * f0.x; acc.y += w * f0.y;
        acc.z += w * f1.x; acc.w += w * f1.y;
    }
    // merge the two halves (lanes L and L+16 hold partial sums for same cols)
    acc.x += __shfl_xor_sync(0xffffffffu, acc.x, 16);
    acc.y += __shfl_xor_sync(0xffffffffu, acc.y, 16);
    acc.z += __shfl_xor_sync(0xffffffffu, acc.z, 16);
    acc.w += __shfl_xor_sync(0xffffffffu, acc.w, 16);

    float di = g_dinv[node];
    float dii = di * di;
    float4 self = ((const float4*)ch)[(size_t)node * 16 + cl];  // fp32 self term
    float4 o;
    o.x = di * acc.x + dii * self.x;
    o.y = di * acc.y + dii * self.y;
    o.z = di * acc.z + dii * self.z;
    o.w = di * acc.w + dii * self.w;
    if (half == 0) {
        ((float4*)nh)[(size_t)node * 16 + cl] = o;
        if (it != NITER - 1)
            nxt[(size_t)node * 16 + cl] = pack_half4(o);
    }

    if (it == NITER - 1) {
        // p[:, -1] = lam*q + q*(1-lam) = q  (leftover dump identity)
        if (lane == 0) p_out[node * NITER + it] = g_q[node];
        return;
    }
    float4 w4 = ((const float4*)hw)[cl];
    float part = o.x * w4.x + o.y * w4.y + o.z * w4.z + o.w * w4.w;
    // lanes 16..31 mirror 0..15; reduce within lower 16
    #pragma unroll
    for (int off = 8; off > 0; off >>= 1)
        part += __shfl_down_sync(0xffffffffu, part, off);
    if (lane == 0) {
        float logit = part + hb[0];
        float lam = 1.0f / (1.0f + __expf(-logit));
        float qv = g_q[node];
        p_out[node * NITER + it] = lam * qv;
        g_q[node] = qv * (1.0f - lam);
    }
}

// ---------------- launch ------------------------------------------------------
// Fork/join under graph capture: CSR chain runs on a side stream concurrently
// with MM1+MM2 on the main (captured) stream; prop waits for both.
extern "C" void kernel_launch(void* const* d_in, const int* in_sizes, int n_in,
                              void* d_out, int out_size) {
    const float* x  = nullptr; const int* ei = nullptr;
    const float* W1 = nullptr; const float* b1 = nullptr;
    const float* W2 = nullptr; const float* b2 = nullptr;
    const float* hw = nullptr; const float* hb = nullptr;
    for (int i = 0; i < n_in; i++) {
        long s = in_sizes[i];
        if      (s == (long)NN * FIN)   x  = (const float*)d_in[i];
        else if (s == 2L * EE)          ei = (const int*)  d_in[i];
        else if (s == (long)FIN * HIDD) W1 = (const float*)d_in[i];
        else if (s == HIDD)             b1 = (const float*)d_in[i];
        else if (s == (long)HIDD*NCLS)  W2 = (const float*)d_in[i];
        else if (s == NCLS) { if (!b2) b2 = (const float*)d_in[i];
                              else     hw = (const float*)d_in[i]; }
    }
    hb = (const float*)d_in[n_in - 1];   // halt_b is the last input

    float* out  = (float*)d_out;
    float* pred = out;                                    // [11, N, 64]
    float* pP   = out + (size_t)(NITER + 1) * NN * NCLS;  // [N, 10]

    // lazily created host-side objects (no device memory; identical enqueued
    // work on every call, so determinism is preserved)
    static cudaStream_t s_csr = nullptr;
    static cudaEvent_t  e_fork = nullptr, e_join = nullptr;
    if (!s_csr) {
        cudaStreamCreateWithFlags(&s_csr, cudaStreamNonBlocking);
        cudaEventCreateWithFlags(&e_fork, cudaEventDisableTiming);
        cudaEventCreateWithFlags(&e_join, cudaEventDisableTiming);
    }

    // fork: CSR chain on side stream
    cudaEventRecord(e_fork, 0);
    cudaStreamWaitEvent(s_csr, e_fork, 0);
    k_init   <<<(NN + 255) / 256, 256, 0, s_csr>>>();
    k_hist   <<<(EE + 255) / 256, 256, 0, s_csr>>>(ei);
    k_scan   <<<1, 1024, 0, s_csr>>>();
    k_scatter<<<(EE + 255) / 256, 256, 0, s_csr>>>(ei);
    cudaEventRecord(e_join, s_csr);

    // main stream: MLP chain (independent of CSR)
    k_mm1<<<dim3(HIDD / 128, (NN + 127) / 128), 256>>>(x, W1, b1);
    k_mm2<<<(NN + 63) / 64, 256>>>(W2, b2, pred);

    // join: prop needs both CSR and pred0
    cudaStreamWaitEvent(0, e_join, 0);
    for (int it = 0; it < NITER; it++) {
        const float* ch = pred + (size_t)it * NN * NCLS;
        float*       nh = pred + (size_t)(it + 1) * NN * NCLS;
        k_prop<<<(NN * 32 + 255) / 256, 256>>>(ch, nh, pP, hw, hb, it);
    }
}

// round 8
// speedup vs baseline: 1.0824x; 1.0824x over previous
#include <cuda_runtime.h>
#include <math.h>
#include <stdint.h>

#define NN    100000
#define EE    3200000
#define FIN   512
#define HIDD  256
#define NCLS  64
#define NITER 10

// ---------------- device scratch (static, no runtime allocation) -------------
__device__ int   g_deg[NN];          // in-degree incl. self loop
__device__ int   g_rowptr[NN + 1];   // CSR row pointers (real edges only)
__device__ int   g_fill[NN];         // scatter cursors
__device__ int2  g_srcw[EE];         // per-edge (source id, dinv[source] bits)
__device__ float g_dinv[NN];         // rsqrt(deg)
__device__ float g_q[NN];            // running halting remainder
__device__ float g_h1[(size_t)NN * HIDD]; // MLP hidden activations

// ---------------- preprocessing ---------------------------------------------
__global__ void k_init() {
    int i = blockIdx.x * blockDim.x + threadIdx.x;
    if (i < NN) { g_deg[i] = 1; g_fill[i] = 0; g_q[i] = 1.0f; }
}

__global__ void k_hist(const int* __restrict__ ei) {
    int e = blockIdx.x * blockDim.x + threadIdx.x;
    if (e < EE) atomicAdd(&g_deg[ei[EE + e]], 1);   // col = target
}

// single-block scan over (deg-1); also computes dinv
__global__ void k_scan() {
    __shared__ int partial[1024];
    const int CH = (NN + 1023) / 1024;      // 98
    int t = threadIdx.x;
    int beg = t * CH;
    int end = min(NN, beg + CH);
    int sum = 0;
    for (int i = beg; i < end; i++) sum += g_deg[i] - 1;
    partial[t] = sum;
    __syncthreads();
    for (int off = 1; off < 1024; off <<= 1) {
        int v = (t >= off) ? partial[t - off] : 0;
        __syncthreads();
        partial[t] += v;
        __syncthreads();
    }
    int excl = (t == 0) ? 0 : partial[t - 1];
    for (int i = beg; i < end; i++) {
        g_rowptr[i] = excl;
        excl += g_deg[i] - 1;
        g_dinv[i] = rsqrtf((float)g_deg[i]);
    }
    if (end == NN) g_rowptr[NN] = excl;     // all tail threads write same total
}

__global__ void k_scatter(const int* __restrict__ ei) {
    int e = blockIdx.x * blockDim.x + threadIdx.x;
    if (e < EE) {
        int c = ei[EE + e];
        int s = ei[e];
        int p = g_rowptr[c] + atomicAdd(&g_fill[c], 1);
        g_srcw[p] = make_int2(s, __float_as_int(g_dinv[s]));
    }
}

// ---------------- tf32 helpers -----------------------------------------------
__device__ __forceinline__ uint32_t f2tf32(float x) {
    uint32_t u;
    asm("cvt.rna.tf32.f32 %0, %1;" : "=r"(u) : "f"(x));
    return u;
}

__device__ __forceinline__ void mma_tf32(float c[4],
                                         uint32_t a0, uint32_t a1, uint32_t a2, uint32_t a3,
                                         uint32_t b0, uint32_t b1) {
    asm volatile("mma.sync.aligned.m16n8k8.row.col.f32.tf32.tf32.f32 "
                 "{%0,%1,%2,%3}, {%4,%5,%6,%7}, {%8,%9}, {%0,%1,%2,%3};"
                 : "+f"(c[0]), "+f"(c[1]), "+f"(c[2]), "+f"(c[3])
                 : "r"(a0), "r"(a1), "r"(a2), "r"(a3), "r"(b0), "r"(b1));
}

// ---------------- MLP1: h1 = relu(x @ W1 + b1), tf32 tensor cores ------------
// 128x128 block tile, BK=16 double-buffered, 8 warps of 64x32.
// grid = (HIDD/128, NN/128): consecutive CTAs share the same X row-tile -> L2 reuse.
#define APAD 20     // As row stride (floats): banks (20g+t)%32 unique -> conflict-free
#define BPAD 136    // Bs row stride (floats): banks (8t+g)%32 unique -> conflict-free
__global__ void __launch_bounds__(256) k_mm1(const float* __restrict__ X,
                                             const float* __restrict__ W1,
                                             const float* __restrict__ b1) {
    __shared__ uint32_t As[2][128][APAD];   // [m][k], tf32 bits
    __shared__ uint32_t Bs[2][16][BPAD];    // [k][n], tf32 bits
    const int bn = blockIdx.x * 128;
    const int bm = blockIdx.y * 128;
    const int tid = threadIdx.x;
    const int wid = tid >> 5, lane = tid & 31;
    const int g = lane >> 2, t = lane & 3;          // groupID, thread-in-group
    const int wm0 = (wid & 1) * 64;                 // warp M origin within block
    const int wn0 = (wid >> 1) * 32;                // warp N origin within block

    float acc[4][4][4] = {};                        // [mt][nt][c0..3]

    // stage loader: gmem -> smem(buf) for k-slice k0
    auto load_stage = [&](int buf, int k0) {
        #pragma unroll
        for (int r = 0; r < 2; r++) {
            int f = tid + r * 256;                  // A: 512 float4
            int row = f >> 2;                       // 4 float4 per 16-wide row
            int kk = (f & 3) * 4;
            int gm = min(bm + row, NN - 1);
            float4 v = *(const float4*)(X + (size_t)gm * FIN + k0 + kk);
            As[buf][row][kk + 0] = f2tf32(v.x);
            As[buf][row][kk + 1] = f2tf32(v.y);
            As[buf][row][kk + 2] = f2tf32(v.z);
            As[buf][row][kk + 3] = f2tf32(v.w);
        }
        #pragma unroll
        for (int r = 0; r < 2; r++) {
            int f = tid + r * 256;                  // B: 512 float4
            int row = f >> 5;                       // 32 float4 per 128-wide row
            int nn = (f & 31) * 4;
            float4 v = *(const float4*)(W1 + (size_t)(k0 + row) * HIDD + bn + nn);
            Bs[buf][row][nn + 0] = f2tf32(v.x);
            Bs[buf][row][nn + 1] = f2tf32(v.y);
            Bs[buf][row][nn + 2] = f2tf32(v.z);
            Bs[buf][row][nn + 3] = f2tf32(v.w);
        }
    };

    load_stage(0, 0);
    __syncthreads();

    const int NSTAGE = FIN / 16;                    // 32
    for (int st = 0; st < NSTAGE; st++) {
        int buf = st & 1;
        if (st + 1 < NSTAGE) load_stage(buf ^ 1, (st + 1) * 16);

        #pragma unroll
        for (int ks = 0; ks < 2; ks++) {
            int kc = ks * 8;
            uint32_t af[4][4];                      // [mt][0..3]
            #pragma unroll
            for (int mt = 0; mt < 4; mt++) {
                int r = wm0 + mt * 16 + g;
                af[mt][0] = As[buf][r][kc + t];
                af[mt][1] = As[buf][r + 8][kc + t];
                af[mt][2] = As[buf][r][kc + t + 4];
                af[mt][3] = As[buf][r + 8][kc + t + 4];
            }
            #pragma unroll
            for (int nt = 0; nt < 4; nt++) {
                int n = wn0 + nt * 8 + g;
                uint32_t b0 = Bs[buf][kc + t][n];
                uint32_t b1f = Bs[buf][kc + t + 4][n];
                #pragma unroll
                for (int mt = 0; mt < 4; mt++)
                    mma_tf32(acc[mt][nt], af[mt][0], af[mt][1], af[mt][2], af[mt][3], b0, b1f);
            }
        }
        __syncthreads();
    }

    // epilogue: bias + relu, direct float2 stores
    #pragma unroll
    for (int nt = 0; nt < 4; nt++) {
        int n = bn + wn0 + nt * 8 + 2 * t;
        float bx = b1[n], by = b1[n + 1];
        #pragma unroll
        for (int mt = 0; mt < 4; mt++) {
            int m0 = bm + wm0 + mt * 16 + g;
            if (m0 < NN) {
                float2 o;
                o.x = fmaxf(acc[mt][nt][0] + bx, 0.0f);
                o.y = fmaxf(acc[mt][nt][1] + by, 0.0f);
                *(float2*)(g_h1 + (size_t)m0 * HIDD + n) = o;
            }
            int m1 = m0 + 8;
            if (m1 < NN) {
                float2 o;
                o.x = fmaxf(acc[mt][nt][2] + bx, 0.0f);
                o.y = fmaxf(acc[mt][nt][3] + by, 0.0f);
                *(float2*)(g_h1 + (size_t)m1 * HIDD + n) = o;
            }
        }
    }
}

// ---------------- MLP2: pred0 = h1 @ W2 + b2 ---------------------------------
// 64-node tile x full 64 cols, BK=64, 256 threads, 4x4 microtile
__global__ void __launch_bounds__(256) k_mm2(const float* __restrict__ W2,
                                             const float* __restrict__ b2,
                                             float* __restrict__ out) {
    __shared__ float Hs[64][64];    // [k][m]
    __shared__ float Ws[64][64];    // [k][n]
    int bm = blockIdx.x * 64;
    int tid = threadIdx.x;
    int tx = tid & 15, ty = tid >> 4;
    float acc[4][4] = {};
    for (int kc = 0; kc < HIDD; kc += 64) {
        #pragma unroll
        for (int r = 0; r < 4; r++) {
            int f = tid + r * 256;          // float4 index 0..1023
            int row = f >> 4;
            int kk = (f & 15) * 4;
            int gm = min(bm + row, NN - 1);
            float4 v = *(const float4*)(g_h1 + (size_t)gm * HIDD + kc + kk);
            Hs[kk + 0][row] = v.x; Hs[kk + 1][row] = v.y;
            Hs[kk + 2][row] = v.z; Hs[kk + 3][row] = v.w;
            float4 wv = *(const float4*)(W2 + (size_t)(kc + row) * NCLS + kk);
            *(float4*)&Ws[row][kk] = wv;
        }
        __syncthreads();
        #pragma unroll
        for (int k = 0; k < 64; k++) {
            float4 av = *(const float4*)&Hs[k][ty * 4];
            float4 bv = *(const float4*)&Ws[k][tx * 4];
            float ra[4] = {av.x, av.y, av.z, av.w};
            float rb[4] = {bv.x, bv.y, bv.z, bv.w};
            #pragma unroll
            for (int i = 0; i < 4; i++)
                #pragma unroll
                for (int j = 0; j < 4; j++)
                    acc[i][j] += ra[i] * rb[j];
        }
        __syncthreads();
    }
    #pragma unroll
    for (int i = 0; i < 4; i++) {
        int m = bm + ty * 4 + i;
        if (m >= NN) continue;
        int n = tx * 4;
        float4 o;
        o.x = acc[i][0] + b2[n + 0];
        o.y = acc[i][1] + b2[n + 1];
        o.z = acc[i][2] + b2[n + 2];
        o.w = acc[i][3] + b2[n + 3];
        *(float4*)(out + (size_t)m * NCLS + n) = o;
    }
}

// ---------------- propagation: one warp per node, 2 edges/step ---------------
// fp32 gathers; edge metadata PREFETCHED one loop iteration ahead so the
// gather of edge i overlaps the metadata load of edge i+1 (breaks the
// meta->gather dependency chain).
__global__ void __launch_bounds__(256) k_prop(const float* __restrict__ ch,
                                              float* __restrict__ nh,
                                              float* __restrict__ p_out,
                                              const float* __restrict__ hw,
                                              const float* __restrict__ hb,
                                              int it) {
    int warp = (blockIdx.x * blockDim.x + threadIdx.x) >> 5;
    if (warp >= NN) return;
    const int lane = threadIdx.x & 31;
    const int half = lane >> 4;          // 0 or 1
    const int cl   = lane & 15;          // float4 column index 0..15
    const int node = warp;
    const int beg = g_rowptr[node];
    const int end = g_rowptr[node + 1];
    const float4* __restrict__ ch4 = (const float4*)ch;

    float4 acc = make_float4(0.0f, 0.0f, 0.0f, 0.0f);

    // prime the prefetch register with this half's first edge
    int s = node; float w = 0.0f;
    {
        int j = beg + half;
        if (j < end) {
            int2 sw = g_srcw[j];
            s = sw.x; w = __int_as_float(sw.y);
        }
    }
    #pragma unroll 4
    for (int j0 = beg; j0 < end; j0 += 2) {
        int   scur = s;
        float wcur = w;
        // prefetch next iteration's metadata (independent of current gather)
        int jn = j0 + 2 + half;
        s = node; w = 0.0f;
        if (jn < end) {
            int2 sw = g_srcw[jn];
            s = sw.x; w = __int_as_float(sw.y);
        }
        float4 v = ch4[(size_t)scur * 16 + cl];
        acc.x += wcur * v.x; acc.y += wcur * v.y;
        acc.z += wcur * v.z; acc.w += wcur * v.w;
    }
    // merge the two halves (lanes L and L+16 hold partial sums for same cols)
    acc.x += __shfl_xor_sync(0xffffffffu, acc.x, 16);
    acc.y += __shfl_xor_sync(0xffffffffu, acc.y, 16);
    acc.z += __shfl_xor_sync(0xffffffffu, acc.z, 16);
    acc.w += __shfl_xor_sync(0xffffffffu, acc.w, 16);

    float di = g_dinv[node];
    float dii = di * di;
    float4 self = ch4[(size_t)node * 16 + cl];
    float4 o;
    o.x = di * acc.x + dii * self.x;
    o.y = di * acc.y + dii * self.y;
    o.z = di * acc.z + dii * self.z;
    o.w = di * acc.w + dii * self.w;
    if (half == 0)
        ((float4*)nh)[(size_t)node * 16 + cl] = o;

    if (it == NITER - 1) {
        // p[:, -1] = lam*q + q*(1-lam) = q  (leftover dump identity)
        if (lane == 0) p_out[node * NITER + it] = g_q[node];
        return;
    }
    float4 w4 = ((const float4*)hw)[cl];
    float part = o.x * w4.x + o.y * w4.y + o.z * w4.z + o.w * w4.w;
    // lanes 16..31 mirror 0..15; reduce within lower 16
    #pragma unroll
    for (int off = 8; off > 0; off >>= 1)
        part += __shfl_down_sync(0xffffffffu, part, off);
    if (lane == 0) {
        float logit = part + hb[0];
        float lam = 1.0f / (1.0f + __expf(-logit));
        float qv = g_q[node];
        p_out[node * NITER + it] = lam * qv;
        g_q[node] = qv * (1.0f - lam);
    }
}

// ---------------- launch ------------------------------------------------------
// Fork/join under graph capture: CSR chain runs on a side stream concurrently
// with MM1+MM2 on the main (captured) stream; prop waits for both.
extern "C" void kernel_launch(void* const* d_in, const int* in_sizes, int n_in,
                              void* d_out, int out_size) {
    const float* x  = nullptr; const int* ei = nullptr;
    const float* W1 = nullptr; const float* b1 = nullptr;
    const float* W2 = nullptr; const float* b2 = nullptr;
    const float* hw = nullptr; const float* hb = nullptr;
    for (int i = 0; i < n_in; i++) {
        long s = in_sizes[i];
        if      (s == (long)NN * FIN)   x  = (const float*)d_in[i];
        else if (s == 2L * EE)          ei = (const int*)  d_in[i];
        else if (s == (long)FIN * HIDD) W1 = (const float*)d_in[i];
        else if (s == HIDD)             b1 = (const float*)d_in[i];
        else if (s == (long)HIDD*NCLS)  W2 = (const float*)d_in[i];
        else if (s == NCLS) { if (!b2) b2 = (const float*)d_in[i];
                              else     hw = (const float*)d_in[i]; }
    }
    hb = (const float*)d_in[n_in - 1];   // halt_b is the last input

    float* out  = (float*)d_out;
    float* pred = out;                                    // [11, N, 64]
    float* pP   = out + (size_t)(NITER + 1) * NN * NCLS;  // [N, 10]

    // lazily created host-side objects (no device memory; identical enqueued
    // work on every call, so determinism is preserved)
    static cudaStream_t s_csr = nullptr;
    static cudaEvent_t  e_fork = nullptr, e_join = nullptr;
    if (!s_csr) {
        cudaStreamCreateWithFlags(&s_csr, cudaStreamNonBlocking);
        cudaEventCreateWithFlags(&e_fork, cudaEventDisableTiming);
        cudaEventCreateWithFlags(&e_join, cudaEventDisableTiming);
    }

    // fork: CSR chain on side stream
    cudaEventRecord(e_fork, 0);
    cudaStreamWaitEvent(s_csr, e_fork, 0);
    k_init   <<<(NN + 255) / 256, 256, 0, s_csr>>>();
    k_hist   <<<(EE + 255) / 256, 256, 0, s_csr>>>(ei);
    k_scan   <<<1, 1024, 0, s_csr>>>();
    k_scatter<<<(EE + 255) / 256, 256, 0, s_csr>>>(ei);
    cudaEventRecord(e_join, s_csr);

    // main stream: MLP chain (independent of CSR)
    k_mm1<<<dim3(HIDD / 128, (NN + 127) / 128), 256>>>(x, W1, b1);
    k_mm2<<<(NN + 63) / 64, 256>>>(W2, b2, pred);

    // join: prop needs both CSR and pred0
    cudaStreamWaitEvent(0, e_join, 0);
    for (int it = 0; it < NITER; it++) {
        const float* ch = pred + (size_t)it * NN * NCLS;
        float*       nh = pred + (size_t)(it + 1) * NN * NCLS;
        k_prop<<<(NN * 32 + 255) / 256, 256>>>(ch, nh, pP, hw, hb, it);
    }
}